// round 8
// baseline (speedup 1.0000x reference)
#include <cuda_runtime.h>
#include <cuda_fp16.h>
#include <cstdint>

// ---------------------------------------------------------------------------
// Linear SSM as truncated causal conv: y[t] = sum_{d<112} K_d x[t-d], K_0+=D.
// Stage 1: fp32 split-K GEMMs with FUSED deterministic last-tile reduction
//          (threadfence + per-tile counter; fixed z-order sum). Power tree
//          trimmed to A^2,A^4,A^8,A^16; V built as serial A^16 chain.
// Stage 2: mma.sync m16n8k16 fp16 conv, ldmatrix.x4 operand loads,
//          K taps via cp.async.bulk 4-stage mbarrier ring. fp32 accumulate.
// ---------------------------------------------------------------------------

#define SEQ   4096
#define BATCH 16
#define DIN   64
#define NST   512
#define DMAX  112
#define TM    128
#define VW    448

#define XSTRH 72            // X smem row stride (halves) -> 144 B
#define KSTRH 72
#define TAPH  4608          // halves per tap (64*72)
#define TAPB  9216          // bytes per tap
#define NSTG  4

#define SM_X    0
#define SM_K    34560       // 240*72*2
#define SM_BAR  71424       // 34560 + 4*9216
#define SM_TOTAL 71552

// fp32 scratch for stage 1
#define OFF_P2   0
#define OFF_P4   262144
#define OFF_P8   524288
#define OFF_P16  786432
#define OFF_W    1572864
#define OFF_V    2097152
#define OFF_SLAB 2326528
#define SCRATCH_FLOATS 4423680     // slab holds up to 8*512*512
__device__ float g_scratch[SCRATCH_FLOATS];

// fp16 tap bank: g_K[d*TAPH + o*KSTRH + i]   ([n][k] layout for B operand)
__device__ __half g_K[DMAX * TAPH];

// per-launch, per-tile arrival counters for fused split-K reduction
__device__ unsigned int g_cnt[14 * 64];

// ---------------- PTX helpers ----------------
__device__ __forceinline__ uint32_t smem_u32(const void* p) {
    uint32_t a;
    asm("{ .reg .u64 t; cvta.to.shared.u64 t, %1; cvt.u32.u64 %0, t; }"
        : "=r"(a) : "l"(p));
    return a;
}
#define MBAR_INIT(addr, cnt) \
    asm volatile("mbarrier.init.shared.b64 [%0], %1;" :: "r"(addr), "r"(cnt) : "memory")
#define MBAR_EXPECT_TX(addr, bytes) \
    asm volatile("mbarrier.arrive.expect_tx.shared.b64 _, [%0], %1;" :: "r"(addr), "r"(bytes) : "memory")
#define MBAR_ARRIVE(addr) \
    asm volatile("mbarrier.arrive.release.cta.shared.b64 _, [%0];" :: "r"(addr) : "memory")
#define MBAR_WAIT(addr, par) do { \
    uint32_t _m = (addr), _p = (par), _d; \
    asm volatile("{\n\t.reg .pred p;\n\t" \
        "mbarrier.try_wait.parity.acquire.cta.shared::cta.b64 p, [%1], %2;\n\t" \
        "selp.b32 %0, 1, 0, p;\n\t}" : "=r"(_d) : "r"(_m), "r"(_p) : "memory"); \
    if (!_d) { \
        asm volatile("{\n\t.reg .pred P1;\n\t" \
            "WL_%=:\n\t" \
            "mbarrier.try_wait.parity.acquire.cta.shared::cta.b64 P1, [%0], %1, 0x989680;\n\t" \
            "@P1 bra.uni WD_%=;\n\t" \
            "bra.uni WL_%=;\n\t" \
            "WD_%=:\n\t}" :: "r"(_m), "r"(_p) : "memory"); \
    } \
} while (0)
__device__ __forceinline__ void bulk_g2s(uint32_t dst, const void* src,
                                         uint32_t bytes, uint32_t mbar) {
    asm volatile("cp.async.bulk.shared::cta.global.mbarrier::complete_tx::bytes "
        "[%0], [%1], %2, [%3];" :: "r"(dst), "l"(src), "r"(bytes), "r"(mbar) : "memory");
}
__device__ __forceinline__ void mma_f16(float* c, uint32_t a0, uint32_t a1,
                                        uint32_t a2, uint32_t a3,
                                        uint32_t b0, uint32_t b1) {
    asm volatile("mma.sync.aligned.m16n8k16.row.col.f32.f16.f16.f32 "
        "{%0,%1,%2,%3}, {%4,%5,%6,%7}, {%8,%9}, {%0,%1,%2,%3};"
        : "+f"(c[0]), "+f"(c[1]), "+f"(c[2]), "+f"(c[3])
        : "r"(a0), "r"(a1), "r"(a2), "r"(a3), "r"(b0), "r"(b1));
}
#define LDSM4(r0, r1, r2, r3, addr) \
    asm volatile("ldmatrix.sync.aligned.m8n8.x4.shared.b16 {%0,%1,%2,%3}, [%4];" \
        : "=r"(r0), "=r"(r1), "=r"(r2), "=r"(r3) : "r"(addr))
__device__ __forceinline__ uint32_t pack_h2(float a, float b) {
    __half2 t;
    t.x = __float2half_rn(a);
    t.y = __float2half_rn(b);
    return *(uint32_t*)&t;
}

// ---------------------------------------------------------------------------
// fp32 split-K GEMM with fused deterministic reduction.
// Slab z computes A[:,zKc:(z+1)Kc] * B[zKc:(z+1)Kc,:] into slab + z*M*N.
// Last CTA per (x,y) tile sums z=0..Z-1 in order and writes dst (ldd).
// Tile 64x64, 256 thr, 4x4 micro. M,N mult of 64 (or M covers full tiles).
// ---------------------------------------------------------------------------
__global__ __launch_bounds__(256) void gemm_sk(
    const float* __restrict__ Ain, const float* __restrict__ Bin,
    float* __restrict__ slab, float* __restrict__ dst,
    int M, int N, int Kc, int lda, int ldb, int ldd, int Z, int cid)
{
    const float* A = Ain + (size_t)blockIdx.z * Kc;
    const float* B = Bin + (size_t)blockIdx.z * Kc * ldb;
    float* out = slab + (size_t)blockIdx.z * M * N;
    __shared__ float As[16][68];
    __shared__ float Bs[16][68];
    const int tid = threadIdx.x;
    const int m0 = blockIdx.y * 64, n0 = blockIdx.x * 64;
    const int tn = tid & 15, tm = tid >> 4;
    const int la_m = (tid * 4) >> 4;
    const int la_k = (tid * 4) & 15;
    const int lb_k = (tid * 4) >> 6;
    const int lb_n = (tid * 4) & 63;
    float acc[4][4] = {};

    for (int k0 = 0; k0 < Kc; k0 += 16) {
        float4 av = *(const float4*)(A + (size_t)(m0 + la_m) * lda + (k0 + la_k));
        As[la_k + 0][la_m] = av.x; As[la_k + 1][la_m] = av.y;
        As[la_k + 2][la_m] = av.z; As[la_k + 3][la_m] = av.w;
        float4 bv = *(const float4*)(B + (size_t)(k0 + lb_k) * ldb + (n0 + lb_n));
        *(float4*)&Bs[lb_k][lb_n] = bv;
        __syncthreads();
        #pragma unroll
        for (int kk = 0; kk < 16; kk++) {
            float4 a = *(const float4*)&As[kk][tm * 4];
            float4 b = *(const float4*)&Bs[kk][tn * 4];
            acc[0][0] += a.x * b.x; acc[0][1] += a.x * b.y; acc[0][2] += a.x * b.z; acc[0][3] += a.x * b.w;
            acc[1][0] += a.y * b.x; acc[1][1] += a.y * b.y; acc[1][2] += a.y * b.z; acc[1][3] += a.y * b.w;
            acc[2][0] += a.z * b.x; acc[2][1] += a.z * b.y; acc[2][2] += a.z * b.z; acc[2][3] += a.z * b.w;
            acc[3][0] += a.w * b.x; acc[3][1] += a.w * b.y; acc[3][2] += a.w * b.z; acc[3][3] += a.w * b.w;
        }
        __syncthreads();
    }
    #pragma unroll
    for (int r = 0; r < 4; r++) {
        float4 o = make_float4(acc[r][0], acc[r][1], acc[r][2], acc[r][3]);
        *(float4*)(out + (size_t)(m0 + tm * 4 + r) * N + (n0 + tn * 4)) = o;
    }

    // fused deterministic reduction: last CTA for this tile sums all z slabs
    __threadfence();
    __shared__ unsigned int oldc;
    const int tile = blockIdx.y * gridDim.x + blockIdx.x;
    if (tid == 0) oldc = atomicAdd(&g_cnt[cid * 64 + tile], 1u);
    __syncthreads();
    if (oldc != (unsigned int)(Z - 1)) return;
    if (tid == 0) g_cnt[cid * 64 + tile] = 0u;   // reset for next graph replay
    __threadfence();

    #pragma unroll
    for (int v = 0; v < 4; v++) {
        int f4 = tid + v * 256;          // 0..1023 float4 slots in 64x64 tile
        int r = f4 >> 4, c4 = (f4 & 15) * 4;
        const float* sp = slab + (size_t)(m0 + r) * N + (n0 + c4);
        float4 s = make_float4(0.f, 0.f, 0.f, 0.f);
        for (int z = 0; z < Z; z++) {
            float4 t = *(const float4*)(sp + (size_t)z * M * N);
            s.x += t.x; s.y += t.y; s.z += t.z; s.w += t.w;
        }
        *(float4*)(dst + (size_t)(m0 + r) * ldd + (n0 + c4)) = s;
    }
}

// ---------------------------------------------------------------------------
// K_d = W_{d&15} * V_{d>>4} (+D for d==0) -> fp16 bank g_K[d][o][i].
// ---------------------------------------------------------------------------
__global__ __launch_bounds__(256) void k_assemble(const float* __restrict__ Dm)
{
    const float* Wc = g_scratch + OFF_W;
    const float* Vc = g_scratch + OFF_V;
    const int d = blockIdx.x;
    const int d1 = d & 15, j = d >> 4;
    const float* A = Wc + (size_t)d1 * 64 * NST;
    const float* B = Vc + j * 64;

    __shared__ float As[16][68];
    __shared__ float Bs[16][68];
    const int tid = threadIdx.x;
    const int tn = tid & 15, tm = tid >> 4;
    const int la_m = (tid * 4) >> 4;
    const int la_k = (tid * 4) & 15;
    const int lb_k = (tid * 4) >> 6;
    const int lb_n = (tid * 4) & 63;
    float acc[4][4] = {};

    for (int k0 = 0; k0 < NST; k0 += 16) {
        float4 av = *(const float4*)(A + (size_t)la_m * NST + (k0 + la_k));
        As[la_k + 0][la_m] = av.x; As[la_k + 1][la_m] = av.y;
        As[la_k + 2][la_m] = av.z; As[la_k + 3][la_m] = av.w;
        float4 bv = *(const float4*)(B + (size_t)(k0 + lb_k) * VW + lb_n);
        *(float4*)&Bs[lb_k][lb_n] = bv;
        __syncthreads();
        #pragma unroll
        for (int kk = 0; kk < 16; kk++) {
            float4 a = *(const float4*)&As[kk][tm * 4];
            float4 b = *(const float4*)&Bs[kk][tn * 4];
            acc[0][0] += a.x * b.x; acc[0][1] += a.x * b.y; acc[0][2] += a.x * b.z; acc[0][3] += a.x * b.w;
            acc[1][0] += a.y * b.x; acc[1][1] += a.y * b.y; acc[1][2] += a.y * b.z; acc[1][3] += a.y * b.w;
            acc[2][0] += a.z * b.x; acc[2][1] += a.z * b.y; acc[2][2] += a.z * b.z; acc[2][3] += a.z * b.w;
            acc[3][0] += a.w * b.x; acc[3][1] += a.w * b.y; acc[3][2] += a.w * b.z; acc[3][3] += a.w * b.w;
        }
        __syncthreads();
    }
    // B-operand layout [o][i] (n-major, k contiguous), fp16
    __half* out = g_K + (size_t)d * TAPH;
    #pragma unroll
    for (int r = 0; r < 4; r++) {
        #pragma unroll
        for (int c = 0; c < 4; c++) {
            int o = tm * 4 + r, i = tn * 4 + c;
            float v = acc[r][c];
            if (d == 0) v += Dm[o * DIN + i];
            out[o * KSTRH + i] = __float2half_rn(v);
        }
    }
}

// ---------------------------------------------------------------------------
// fp16 mma.sync conv with ldmatrix.x4 operand loads.
// 256 thr = 8 warps, each computing a 16t x 64o tile.
// ---------------------------------------------------------------------------
__global__ __launch_bounds__(256, 2) void conv_tc(const float* __restrict__ x,
                                                  float* __restrict__ y)
{
    extern __shared__ char sm[];
    __half* Xs = (__half*)(sm + SM_X);
    const uint32_t sb = smem_u32(sm);
    const uint32_t barF = sb + SM_BAR;        // full[0..3] at +0,8,16,24
    const uint32_t barE = sb + SM_BAR + 32;   // empty[0..3]
    const int tid = threadIdx.x;
    const int wid = tid >> 5, lane = tid & 31;
    const int gid = lane >> 2, tig = lane & 3;
    const int b = blockIdx.y;
    const int t0 = blockIdx.x * TM;

    if (tid == 0) {
        #pragma unroll
        for (int s = 0; s < NSTG; s++) {
            MBAR_INIT(barF + s * 8, 1);
            MBAR_INIT(barE + s * 8, 8);
        }
    }
    __syncthreads();

    // kick off first NSTG tap fills
    if (tid == 0) {
        #pragma unroll
        for (int s = 0; s < NSTG; s++) {
            MBAR_EXPECT_TX(barF + s * 8, TAPB);
            bulk_g2s(sb + SM_K + s * TAPB, g_K + (size_t)s * TAPH, TAPB, barF + s * 8);
        }
    }

    // stage X window fp16: row u <-> global t = t0 - 111 + u, u in [0,239)
    for (int u = tid; u < 239; u += 256) {
        int tg = t0 - (DMAX - 1) + u;
        uint32_t* dst = (uint32_t*)(Xs + u * XSTRH);
        if (tg >= 0) {
            const float4* src = (const float4*)(x + ((size_t)b * SEQ + tg) * DIN);
            #pragma unroll
            for (int c = 0; c < 16; c += 2) {
                float4 v0 = src[c], v1 = src[c + 1];
                uint4 h;
                h.x = pack_h2(v0.x, v0.y); h.y = pack_h2(v0.z, v0.w);
                h.z = pack_h2(v1.x, v1.y); h.w = pack_h2(v1.z, v1.w);
                *(uint4*)(dst + c * 2) = h;
            }
        } else {
            #pragma unroll
            for (int c = 0; c < 8; c++)
                *(uint4*)(dst + c * 4) = make_uint4(0, 0, 0, 0);
        }
    }
    __syncthreads();

    float acc[8][4];
    #pragma unroll
    for (int nf = 0; nf < 8; nf++) {
        acc[nf][0] = 0.f; acc[nf][1] = 0.f; acc[nf][2] = 0.f; acc[nf][3] = 0.f;
    }

    // ldmatrix per-lane address invariants (byte offsets; row stride 144B)
    const uint32_t invA = (uint32_t)(wid * 16 + (lane & 15)) * 144u
                        + (uint32_t)(lane >> 4) * 16u;
    const uint32_t invB = (uint32_t)((lane & 7) + ((lane >> 4) << 3)) * 144u
                        + (uint32_t)((lane >> 3) & 1) * 16u;

    for (int d = 0; d < DMAX; d++) {
        const int s = d & 3;
        const uint32_t par = (d >> 2) & 1;
        MBAR_WAIT(barF + s * 8, par);

        const uint32_t aBase = sb + SM_X + invA + (uint32_t)(DMAX - 1 - d) * 144u;
        const uint32_t bBase = sb + SM_K + (uint32_t)s * TAPB + invB;

        #pragma unroll
        for (int kc = 0; kc < 4; kc++) {
            uint32_t a0, a1, a2, a3;
            LDSM4(a0, a1, a2, a3, aBase + kc * 32);
            #pragma unroll
            for (int nfp = 0; nfp < 4; nfp++) {
                uint32_t b0, b1, b2, b3;
                LDSM4(b0, b1, b2, b3, bBase + nfp * 2304 + kc * 32);
                mma_f16(acc[2 * nfp],     a0, a1, a2, a3, b0, b1);
                mma_f16(acc[2 * nfp + 1], a0, a1, a2, a3, b2, b3);
            }
        }

        if (lane == 0) MBAR_ARRIVE(barE + s * 8);
        if (tid == 0 && d + NSTG < DMAX) {
            MBAR_WAIT(barE + s * 8, par);
            MBAR_EXPECT_TX(barF + s * 8, TAPB);
            bulk_g2s(sb + SM_K + s * TAPB, g_K + (size_t)(d + NSTG) * TAPH, TAPB,
                     barF + s * 8);
        }
    }

    // epilogue: D frag rows gid, gid+8; cols 2*tig, 2*tig+1 per 8-col nfrag
    const int r0 = t0 + wid * 16 + gid;
    #pragma unroll
    for (int nf = 0; nf < 8; nf++) {
        int col = nf * 8 + 2 * tig;
        *(float2*)(y + ((size_t)b * SEQ + r0) * DIN + col) =
            make_float2(acc[nf][0], acc[nf][1]);
        *(float2*)(y + ((size_t)b * SEQ + r0 + 8) * DIN + col) =
            make_float2(acc[nf][2], acc[nf][3]);
    }
}

// ---------------------------------------------------------------------------
extern "C" void kernel_launch(void* const* d_in, const int* in_sizes, int n_in,
                              void* d_out, int out_size)
{
    const float* x  = (const float*)d_in[0];
    const float* A  = (const float*)d_in[1];
    const float* Bm = (const float*)d_in[2];
    const float* Cm = (const float*)d_in[3];
    const float* Dm = (const float*)d_in[4];
    float* y = (float*)d_out;

    float* s = nullptr;
    cudaGetSymbolAddress((void**)&s, g_scratch);
    float* P2  = s + OFF_P2;  float* P4  = s + OFF_P4;
    float* P8  = s + OFF_P8;  float* P16 = s + OFF_P16;
    float* W   = s + OFF_W;   float* V   = s + OFF_V;
    float* SL  = s + OFF_SLAB;

    cudaFuncSetAttribute(conv_tc, cudaFuncAttributeMaxDynamicSharedMemorySize, SM_TOTAL);

    // seed W row-block 0 <- C ; V col-block 0 <- B
    cudaMemcpyAsync(W, Cm, (size_t)64 * NST * sizeof(float), cudaMemcpyDeviceToDevice);
    cudaMemcpy2DAsync(V, VW * sizeof(float), Bm, 64 * sizeof(float),
                      64 * sizeof(float), NST, cudaMemcpyDeviceToDevice);

    dim3 thr(256);
    // powers: A^2, A^4, A^8, A^16 (fused split-K z=8)
    gemm_sk<<<dim3(8,8,8), thr>>>(A,   A,   SL, P2,  512, 512, 64, 512, 512, 512, 8, 0);
    gemm_sk<<<dim3(8,8,8), thr>>>(P2,  P2,  SL, P4,  512, 512, 64, 512, 512, 512, 8, 1);
    gemm_sk<<<dim3(8,8,8), thr>>>(P4,  P4,  SL, P8,  512, 512, 64, 512, 512, 512, 8, 2);
    gemm_sk<<<dim3(8,8,8), thr>>>(P8,  P8,  SL, P16, 512, 512, 64, 512, 512, 512, 8, 3);
    // W stack doubling: W_d = C A^d, d = 0..15 (rows d*64)
    gemm_sk<<<dim3(8,1,8), thr>>>(W, A,  SL, W + (size_t)64  * 512,  64, 512, 64, 512, 512, 512, 8, 4);
    gemm_sk<<<dim3(8,2,8), thr>>>(W, P2, SL, W + (size_t)128 * 512, 128, 512, 64, 512, 512, 512, 8, 5);
    gemm_sk<<<dim3(8,4,8), thr>>>(W, P4, SL, W + (size_t)256 * 512, 256, 512, 64, 512, 512, 512, 8, 6);
    gemm_sk<<<dim3(8,8,8), thr>>>(W, P8, SL, W + (size_t)512 * 512, 512, 512, 64, 512, 512, 512, 8, 7);
    // V chain: V_{j+1} = A^16 V_j (col blocks of width 64 in Vcat, ld=VW)
    for (int j = 0; j < 6; j++)
        gemm_sk<<<dim3(1,8,8), thr>>>(P16, V + j * 64, SL, V + (j + 1) * 64,
                                      512, 64, 64, 512, VW, VW, 8, 8 + j);

    // tap bank (fp16, B-operand layout, D folded into tap 0)
    k_assemble<<<DMAX, thr>>>(Dm);
    // tensor-core convolution (mma.sync fp16 + ldmatrix, fp32 accumulate)
    conv_tc<<<dim3(SEQ / TM, BATCH), 256, SM_TOTAL>>>(x, y);
}

// round 9
// speedup vs baseline: 1.1549x; 1.1549x over previous
#include <cuda_runtime.h>
#include <cuda_fp16.h>
#include <cstdint>

// ---------------------------------------------------------------------------
// Linear SSM as truncated causal conv: y[t] = sum_{d<112} K_d x[t-d], K_0+=D.
// Stage 1: ONE persistent kernel (288 CTAs, software grid barrier) runs the
//          whole GEMM DAG: powers A^2..A^64 || W-stack doubling || V-stack,
//          split-K slabs reduced in fixed z-order, then k_assemble -> fp16
//          tap bank. Deterministic; no launch gaps.
// Stage 2: mma.sync m16n8k16 fp16 conv (validated), ldmatrix.x4 operands,
//          K taps via cp.async.bulk 4-stage mbarrier ring. fp32 accumulate.
// ---------------------------------------------------------------------------

#define SEQ   4096
#define BATCH 16
#define DIN   64
#define NST   512
#define DMAX  112
#define TM    128
#define VW    448

#define XSTRH 72
#define KSTRH 72
#define TAPH  4608
#define TAPB  9216
#define NSTG  4

#define SM_X    0
#define SM_K    34560
#define SM_BAR  71424
#define SM_TOTAL 71552

#define NCTA  288

// fp32 scratch
#define OFF_P2   0
#define OFF_P4   262144
#define OFF_P8   524288
#define OFF_P16  786432
#define OFF_P32  1048576
#define OFF_P64  1310720
#define OFF_W    1572864
#define OFF_V    2097152
#define OFF_S0   2326528
#define OFF_S1   3375104
#define SCRATCH_FLOATS 4423680
__device__ float g_scratch[SCRATCH_FLOATS];

// fp16 tap bank: g_K[d*TAPH + o*KSTRH + i]
__device__ __half g_K[DMAX * TAPH];

// grid barrier state
__device__ unsigned int g_arrive;
__device__ volatile unsigned int g_epoch;

// ---------------- PTX helpers ----------------
__device__ __forceinline__ uint32_t smem_u32(const void* p) {
    uint32_t a;
    asm("{ .reg .u64 t; cvta.to.shared.u64 t, %1; cvt.u32.u64 %0, t; }"
        : "=r"(a) : "l"(p));
    return a;
}
#define MBAR_INIT(addr, cnt) \
    asm volatile("mbarrier.init.shared.b64 [%0], %1;" :: "r"(addr), "r"(cnt) : "memory")
#define MBAR_EXPECT_TX(addr, bytes) \
    asm volatile("mbarrier.arrive.expect_tx.shared.b64 _, [%0], %1;" :: "r"(addr), "r"(bytes) : "memory")
#define MBAR_ARRIVE(addr) \
    asm volatile("mbarrier.arrive.release.cta.shared.b64 _, [%0];" :: "r"(addr) : "memory")
#define MBAR_WAIT(addr, par) do { \
    uint32_t _m = (addr), _p = (par), _d; \
    asm volatile("{\n\t.reg .pred p;\n\t" \
        "mbarrier.try_wait.parity.acquire.cta.shared::cta.b64 p, [%1], %2;\n\t" \
        "selp.b32 %0, 1, 0, p;\n\t}" : "=r"(_d) : "r"(_m), "r"(_p) : "memory"); \
    if (!_d) { \
        asm volatile("{\n\t.reg .pred P1;\n\t" \
            "WL_%=:\n\t" \
            "mbarrier.try_wait.parity.acquire.cta.shared::cta.b64 P1, [%0], %1, 0x989680;\n\t" \
            "@P1 bra.uni WD_%=;\n\t" \
            "bra.uni WL_%=;\n\t" \
            "WD_%=:\n\t}" :: "r"(_m), "r"(_p) : "memory"); \
    } \
} while (0)
__device__ __forceinline__ void bulk_g2s(uint32_t dst, const void* src,
                                         uint32_t bytes, uint32_t mbar) {
    asm volatile("cp.async.bulk.shared::cta.global.mbarrier::complete_tx::bytes "
        "[%0], [%1], %2, [%3];" :: "r"(dst), "l"(src), "r"(bytes), "r"(mbar) : "memory");
}
__device__ __forceinline__ void mma_f16(float* c, uint32_t a0, uint32_t a1,
                                        uint32_t a2, uint32_t a3,
                                        uint32_t b0, uint32_t b1) {
    asm volatile("mma.sync.aligned.m16n8k16.row.col.f32.f16.f16.f32 "
        "{%0,%1,%2,%3}, {%4,%5,%6,%7}, {%8,%9}, {%0,%1,%2,%3};"
        : "+f"(c[0]), "+f"(c[1]), "+f"(c[2]), "+f"(c[3])
        : "r"(a0), "r"(a1), "r"(a2), "r"(a3), "r"(b0), "r"(b1));
}
#define LDSM4(r0, r1, r2, r3, addr) \
    asm volatile("ldmatrix.sync.aligned.m8n8.x4.shared.b16 {%0,%1,%2,%3}, [%4];" \
        : "=r"(r0), "=r"(r1), "=r"(r2), "=r"(r3) : "r"(addr))
__device__ __forceinline__ uint32_t pack_h2(float a, float b) {
    __half2 t;
    t.x = __float2half_rn(a);
    t.y = __float2half_rn(b);
    return *(uint32_t*)&t;
}

// ---------------------------------------------------------------------------
// grid barrier (sense-reversing epoch; deterministic)
// ---------------------------------------------------------------------------
__device__ __noinline__ void gbar() {
    __syncthreads();
    if (threadIdx.x == 0) {
        __threadfence();
        unsigned int e = g_epoch;
        if (atomicAdd(&g_arrive, 1u) == NCTA - 1u) {
            g_arrive = 0u;
            __threadfence();
            atomicAdd((unsigned int*)&g_epoch, 1u);
        } else {
            while (g_epoch == e) __nanosleep(64);
        }
        __threadfence();
    }
    __syncthreads();
}

// ---------------------------------------------------------------------------
// 64x64 fp32 GEMM tile over K range [koff, koff+Kc): out[(m0+r)*ldo + n0+c]
// ---------------------------------------------------------------------------
__device__ __noinline__ void tileGemm(
    const float* __restrict__ A, const float* __restrict__ B,
    float* __restrict__ out, int ldo, int m0, int n0, int Kc, int koff,
    int lda, int ldb, float (*As)[68], float (*Bs)[68])
{
    const int tid = threadIdx.x;
    const int tn = tid & 15, tm = tid >> 4;
    const int la_m = (tid * 4) >> 4;
    const int la_k = (tid * 4) & 15;
    const int lb_k = (tid * 4) >> 6;
    const int lb_n = (tid * 4) & 63;
    float acc[4][4] = {};

    for (int k0 = koff; k0 < koff + Kc; k0 += 16) {
        float4 av = *(const float4*)(A + (size_t)(m0 + la_m) * lda + (k0 + la_k));
        As[la_k + 0][la_m] = av.x; As[la_k + 1][la_m] = av.y;
        As[la_k + 2][la_m] = av.z; As[la_k + 3][la_m] = av.w;
        float4 bv = *(const float4*)(B + (size_t)(k0 + lb_k) * ldb + (n0 + lb_n));
        *(float4*)&Bs[lb_k][lb_n] = bv;
        __syncthreads();
        #pragma unroll
        for (int kk = 0; kk < 16; kk++) {
            float4 a = *(const float4*)&As[kk][tm * 4];
            float4 b = *(const float4*)&Bs[kk][tn * 4];
            acc[0][0] += a.x * b.x; acc[0][1] += a.x * b.y; acc[0][2] += a.x * b.z; acc[0][3] += a.x * b.w;
            acc[1][0] += a.y * b.x; acc[1][1] += a.y * b.y; acc[1][2] += a.y * b.z; acc[1][3] += a.y * b.w;
            acc[2][0] += a.z * b.x; acc[2][1] += a.z * b.y; acc[2][2] += a.z * b.z; acc[2][3] += a.z * b.w;
            acc[3][0] += a.w * b.x; acc[3][1] += a.w * b.y; acc[3][2] += a.w * b.z; acc[3][3] += a.w * b.w;
        }
        __syncthreads();
    }
    #pragma unroll
    for (int r = 0; r < 4; r++) {
        float4 o = make_float4(acc[r][0], acc[r][1], acc[r][2], acc[r][3]);
        *(float4*)(out + (size_t)(m0 + tm * 4 + r) * ldo + (n0 + tn * 4)) = o;
    }
}

// ---------------------------------------------------------------------------
// fixed z-order slab reduction of f4 range [f4base, f4base+f4cnt)
// slab rows dense width N; dst leading dim ldd.
// ---------------------------------------------------------------------------
__device__ __noinline__ void redAdd(
    const float* __restrict__ slab, float* __restrict__ dst,
    int ldd, int N, size_t zstride, int Z, int f4base, int f4cnt)
{
    const int fpr = N >> 2;
    for (int i = f4base + threadIdx.x; i < f4base + f4cnt; i += 256) {
        int r = i / fpr, c4 = (i - r * fpr) * 4;
        const float* sp = slab + (size_t)r * N + c4;
        float sx = 0.f, sy = 0.f, sz = 0.f, sw = 0.f;
        for (int z = 0; z < Z; z++) {
            float4 t = *(const float4*)(sp + zstride * z);
            sx += t.x; sy += t.y; sz += t.z; sw += t.w;
        }
        *(float4*)(dst + (size_t)r * ldd + c4) = make_float4(sx, sy, sz, sw);
    }
}

// ---------------------------------------------------------------------------
// K_d = W_{d&15} * V_{d>>4} (+D for d==0) -> fp16 bank g_K[d][o][i].
// ---------------------------------------------------------------------------
__device__ __noinline__ void kasm(int d, const float* __restrict__ Dm,
                                  float (*As)[68], float (*Bs)[68])
{
    const float* Wc = g_scratch + OFF_W;
    const float* Vc = g_scratch + OFF_V;
    const int d1 = d & 15, j = d >> 4;
    const float* A = Wc + (size_t)d1 * 64 * NST;
    const float* B = Vc + j * 64;

    const int tid = threadIdx.x;
    const int tn = tid & 15, tm = tid >> 4;
    const int la_m = (tid * 4) >> 4;
    const int la_k = (tid * 4) & 15;
    const int lb_k = (tid * 4) >> 6;
    const int lb_n = (tid * 4) & 63;
    float acc[4][4] = {};

    for (int k0 = 0; k0 < NST; k0 += 16) {
        float4 av = *(const float4*)(A + (size_t)la_m * NST + (k0 + la_k));
        As[la_k + 0][la_m] = av.x; As[la_k + 1][la_m] = av.y;
        As[la_k + 2][la_m] = av.z; As[la_k + 3][la_m] = av.w;
        float4 bv = *(const float4*)(B + (size_t)(k0 + lb_k) * VW + lb_n);
        *(float4*)&Bs[lb_k][lb_n] = bv;
        __syncthreads();
        #pragma unroll
        for (int kk = 0; kk < 16; kk++) {
            float4 a = *(const float4*)&As[kk][tm * 4];
            float4 b = *(const float4*)&Bs[kk][tn * 4];
            acc[0][0] += a.x * b.x; acc[0][1] += a.x * b.y; acc[0][2] += a.x * b.z; acc[0][3] += a.x * b.w;
            acc[1][0] += a.y * b.x; acc[1][1] += a.y * b.y; acc[1][2] += a.y * b.z; acc[1][3] += a.y * b.w;
            acc[2][0] += a.z * b.x; acc[2][1] += a.z * b.y; acc[2][2] += a.z * b.z; acc[2][3] += a.z * b.w;
            acc[3][0] += a.w * b.x; acc[3][1] += a.w * b.y; acc[3][2] += a.w * b.z; acc[3][3] += a.w * b.w;
        }
        __syncthreads();
    }
    __half* out = g_K + (size_t)d * TAPH;
    #pragma unroll
    for (int r = 0; r < 4; r++) {
        #pragma unroll
        for (int c = 0; c < 4; c++) {
            int o = tm * 4 + r, i = tn * 4 + c;
            float v = acc[r][c];
            if (d == 0) v += Dm[o * DIN + i];
            out[o * KSTRH + i] = __float2half_rn(v);
        }
    }
}

// ---------------------------------------------------------------------------
// Persistent stage-1 kernel: entire GEMM DAG + k_assemble in one launch.
// ---------------------------------------------------------------------------
__global__ __launch_bounds__(256, 2) void stage1(const float* __restrict__ A,
                                                 const float* __restrict__ Dm)
{
    __shared__ float As[16][68];
    __shared__ float Bs[16][68];
    float* S   = g_scratch;
    float* P2  = S + OFF_P2;  float* P4  = S + OFF_P4;
    float* P8  = S + OFF_P8;  float* P16 = S + OFF_P16;
    float* P32 = S + OFF_P32; float* P64 = S + OFF_P64;
    float* W   = S + OFF_W;   float* V   = S + OFF_V;
    float* S0  = S + OFF_S0;  float* S1  = S + OFF_S1;
    const int bid = blockIdx.x;

    // G1: P2 = A*A (z=4) || W1 = C*A (z=4)
    if (bid < 256) {
        int t = bid & 63, z = bid >> 6;
        tileGemm(A, A, S0 + (size_t)z * 262144, 512, (t >> 3) * 64, (t & 7) * 64,
                 128, z * 128, 512, 512, As, Bs);
    } else {
        int t = bid - 256, ti = t & 7, z = t >> 3;
        tileGemm(W, A, S1 + (size_t)z * 32768, 512, 0, ti * 64,
                 128, z * 128, 512, 512, As, Bs);
    }
    gbar();
    // R1
    if (bid < 256) redAdd(S0, P2, 512, 512, 262144, 4, bid * 256, 256);
    else           redAdd(S1, W + (size_t)64 * 512, 512, 512, 32768, 4, (bid - 256) * 256, 256);
    gbar();

    // G2: P4 = P2^2 (z=4) || W2 = W[0:128)*P2 (z=2)
    if (bid < 256) {
        int t = bid & 63, z = bid >> 6;
        tileGemm(P2, P2, S0 + (size_t)z * 262144, 512, (t >> 3) * 64, (t & 7) * 64,
                 128, z * 128, 512, 512, As, Bs);
    } else {
        int t = bid - 256, tile = t & 15, z = t >> 4;
        tileGemm(W, P2, S1 + (size_t)z * 65536, 512, (tile >> 3) * 64, (tile & 7) * 64,
                 256, z * 256, 512, 512, As, Bs);
    }
    gbar();
    if (bid < 256) redAdd(S0, P4, 512, 512, 262144, 4, bid * 256, 256);
    else           redAdd(S1, W + (size_t)128 * 512, 512, 512, 65536, 2, (bid - 256) * 512, 512);
    gbar();

    // G3: P8 = P4^2 (z=2, 128 CTAs) || W3 = W[0:256)*P4 (z=4, 128 CTAs)
    if (bid < 128) {
        int t = bid & 63, z = bid >> 6;
        tileGemm(P4, P4, S0 + (size_t)z * 262144, 512, (t >> 3) * 64, (t & 7) * 64,
                 256, z * 256, 512, 512, As, Bs);
    } else if (bid < 256) {
        int t = bid - 128, tile = t & 31, z = t >> 5;
        tileGemm(W, P4, S1 + (size_t)z * 131072, 512, (tile >> 3) * 64, (tile & 7) * 64,
                 128, z * 128, 512, 512, As, Bs);
    }
    gbar();
    if (bid < 128)      redAdd(S0, P8, 512, 512, 262144, 2, bid * 512, 512);
    else if (bid < 256) redAdd(S1, W + (size_t)256 * 512, 512, 512, 131072, 4, (bid - 128) * 256, 256);
    gbar();

    // G4: P16 = P8^2 (z=2, 128 CTAs) || W4 = W[0:512)*P8 (z=2, 128 CTAs)
    if (bid < 128) {
        int t = bid & 63, z = bid >> 6;
        tileGemm(P8, P8, S0 + (size_t)z * 262144, 512, (t >> 3) * 64, (t & 7) * 64,
                 256, z * 256, 512, 512, As, Bs);
    } else if (bid < 256) {
        int t = bid - 128, tile = t & 63, z = t >> 6;
        tileGemm(W, P8, S1 + (size_t)z * 262144, 512, (tile >> 3) * 64, (tile & 7) * 64,
                 256, z * 256, 512, 512, As, Bs);
    }
    gbar();
    if (bid < 128)      redAdd(S0, P16, 512, 512, 262144, 2, bid * 512, 512);
    else if (bid < 256) redAdd(S1, W + (size_t)512 * 512, 512, 512, 262144, 2, (bid - 128) * 512, 512);
    gbar();

    // G5: P32 = P16^2 (z=4) || V1 = P16*V0 (z=4)
    if (bid < 256) {
        int t = bid & 63, z = bid >> 6;
        tileGemm(P16, P16, S0 + (size_t)z * 262144, 512, (t >> 3) * 64, (t & 7) * 64,
                 128, z * 128, 512, 512, As, Bs);
    } else {
        int t = bid - 256, ti = t & 7, z = t >> 3;
        tileGemm(P16, V, S1 + (size_t)z * 32768, 64, ti * 64, 0,
                 128, z * 128, 512, VW, As, Bs);
    }
    gbar();
    if (bid < 256) redAdd(S0, P32, 512, 512, 262144, 4, bid * 256, 256);
    else           redAdd(S1, V + 64, VW, 64, 32768, 4, (bid - 256) * 256, 256);
    gbar();

    // G6: P64 = P32^2 (z=4) || V23 = P32*V[0:128) (z=2)
    if (bid < 256) {
        int t = bid & 63, z = bid >> 6;
        tileGemm(P32, P32, S0 + (size_t)z * 262144, 512, (t >> 3) * 64, (t & 7) * 64,
                 128, z * 128, 512, 512, As, Bs);
    } else {
        int t = bid - 256, tile = t & 15, z = t >> 4;
        tileGemm(P32, V, S1 + (size_t)z * 65536, 128, (tile >> 1) * 64, (tile & 1) * 64,
                 256, z * 256, 512, VW, As, Bs);
    }
    gbar();
    if (bid < 256) redAdd(S0, P64, 512, 512, 262144, 4, bid * 256, 256);
    else           redAdd(S1, V + 128, VW, 128, 65536, 2, (bid - 256) * 512, 512);
    gbar();

    // G7: V456 = P64*V[0:192) (z=8, 192 CTAs)
    if (bid < 192) {
        int z = bid / 24, tile = bid % 24;
        tileGemm(P64, V, S0 + (size_t)z * 98304, 192, (tile / 3) * 64, (tile % 3) * 64,
                 64, z * 64, 512, VW, As, Bs);
    }
    gbar();
    if (bid < 192) redAdd(S0, V + 256, VW, 192, 98304, 8, bid * 128, 128);
    gbar();

    // G8: tap bank
    if (bid < DMAX) kasm(bid, Dm, As, Bs);
}

// ---------------------------------------------------------------------------
// fp16 mma.sync conv with ldmatrix.x4 operand loads (validated, unchanged).
// ---------------------------------------------------------------------------
__global__ __launch_bounds__(256, 2) void conv_tc(const float* __restrict__ x,
                                                  float* __restrict__ y)
{
    extern __shared__ char sm[];
    __half* Xs = (__half*)(sm + SM_X);
    const uint32_t sb = smem_u32(sm);
    const uint32_t barF = sb + SM_BAR;
    const uint32_t barE = sb + SM_BAR + 32;
    const int tid = threadIdx.x;
    const int wid = tid >> 5, lane = tid & 31;
    const int gid = lane >> 2, tig = lane & 3;
    const int b = blockIdx.y;
    const int t0 = blockIdx.x * TM;

    if (tid == 0) {
        #pragma unroll
        for (int s = 0; s < NSTG; s++) {
            MBAR_INIT(barF + s * 8, 1);
            MBAR_INIT(barE + s * 8, 8);
        }
    }
    __syncthreads();

    if (tid == 0) {
        #pragma unroll
        for (int s = 0; s < NSTG; s++) {
            MBAR_EXPECT_TX(barF + s * 8, TAPB);
            bulk_g2s(sb + SM_K + s * TAPB, g_K + (size_t)s * TAPH, TAPB, barF + s * 8);
        }
    }

    for (int u = tid; u < 239; u += 256) {
        int tg = t0 - (DMAX - 1) + u;
        uint32_t* dst = (uint32_t*)(Xs + u * XSTRH);
        if (tg >= 0) {
            const float4* src = (const float4*)(x + ((size_t)b * SEQ + tg) * DIN);
            #pragma unroll
            for (int c = 0; c < 16; c += 2) {
                float4 v0 = src[c], v1 = src[c + 1];
                uint4 h;
                h.x = pack_h2(v0.x, v0.y); h.y = pack_h2(v0.z, v0.w);
                h.z = pack_h2(v1.x, v1.y); h.w = pack_h2(v1.z, v1.w);
                *(uint4*)(dst + c * 2) = h;
            }
        } else {
            #pragma unroll
            for (int c = 0; c < 8; c++)
                *(uint4*)(dst + c * 4) = make_uint4(0, 0, 0, 0);
        }
    }
    __syncthreads();

    float acc[8][4];
    #pragma unroll
    for (int nf = 0; nf < 8; nf++) {
        acc[nf][0] = 0.f; acc[nf][1] = 0.f; acc[nf][2] = 0.f; acc[nf][3] = 0.f;
    }

    const uint32_t invA = (uint32_t)(wid * 16 + (lane & 15)) * 144u
                        + (uint32_t)(lane >> 4) * 16u;
    const uint32_t invB = (uint32_t)((lane & 7) + ((lane >> 4) << 3)) * 144u
                        + (uint32_t)((lane >> 3) & 1) * 16u;

    for (int d = 0; d < DMAX; d++) {
        const int s = d & 3;
        const uint32_t par = (d >> 2) & 1;
        MBAR_WAIT(barF + s * 8, par);

        const uint32_t aBase = sb + SM_X + invA + (uint32_t)(DMAX - 1 - d) * 144u;
        const uint32_t bBase = sb + SM_K + (uint32_t)s * TAPB + invB;

        #pragma unroll
        for (int kc = 0; kc < 4; kc++) {
            uint32_t a0, a1, a2, a3;
            LDSM4(a0, a1, a2, a3, aBase + kc * 32);
            #pragma unroll
            for (int nfp = 0; nfp < 4; nfp++) {
                uint32_t b0, b1, b2, b3;
                LDSM4(b0, b1, b2, b3, bBase + nfp * 2304 + kc * 32);
                mma_f16(acc[2 * nfp],     a0, a1, a2, a3, b0, b1);
                mma_f16(acc[2 * nfp + 1], a0, a1, a2, a3, b2, b3);
            }
        }

        if (lane == 0) MBAR_ARRIVE(barE + s * 8);
        if (tid == 0 && d + NSTG < DMAX) {
            MBAR_WAIT(barE + s * 8, par);
            MBAR_EXPECT_TX(barF + s * 8, TAPB);
            bulk_g2s(sb + SM_K + s * TAPB, g_K + (size_t)(d + NSTG) * TAPH, TAPB,
                     barF + s * 8);
        }
    }

    const int r0 = t0 + wid * 16 + gid;
    #pragma unroll
    for (int nf = 0; nf < 8; nf++) {
        int col = nf * 8 + 2 * tig;
        *(float2*)(y + ((size_t)b * SEQ + r0) * DIN + col) =
            make_float2(acc[nf][0], acc[nf][1]);
        *(float2*)(y + ((size_t)b * SEQ + r0 + 8) * DIN + col) =
            make_float2(acc[nf][2], acc[nf][3]);
    }
}

// ---------------------------------------------------------------------------
extern "C" void kernel_launch(void* const* d_in, const int* in_sizes, int n_in,
                              void* d_out, int out_size)
{
    const float* x  = (const float*)d_in[0];
    const float* A  = (const float*)d_in[1];
    const float* Bm = (const float*)d_in[2];
    const float* Cm = (const float*)d_in[3];
    const float* Dm = (const float*)d_in[4];
    float* y = (float*)d_out;

    float* s = nullptr;
    cudaGetSymbolAddress((void**)&s, g_scratch);
    float* W = s + OFF_W;
    float* V = s + OFF_V;

    cudaFuncSetAttribute(conv_tc, cudaFuncAttributeMaxDynamicSharedMemorySize, SM_TOTAL);

    // seed W row-block 0 <- C ; V col-block 0 <- B
    cudaMemcpyAsync(W, Cm, (size_t)64 * NST * sizeof(float), cudaMemcpyDeviceToDevice);
    cudaMemcpy2DAsync(V, VW * sizeof(float), Bm, 64 * sizeof(float),
                      64 * sizeof(float), NST, cudaMemcpyDeviceToDevice);

    // whole stage 1 in one persistent launch
    stage1<<<NCTA, 256>>>(A, Dm);

    // tensor-core convolution
    conv_tc<<<dim3(SEQ / TM, BATCH), 256, SM_TOTAL>>>(x, y);
}

// round 10
// speedup vs baseline: 1.2841x; 1.1118x over previous
#include <cuda_runtime.h>
#include <cuda_fp16.h>
#include <cstdint>

// ---------------------------------------------------------------------------
// Linear SSM as truncated causal conv: y[t] = sum_{d<112} K_d x[t-d], K_0+=D.
// Stage 1: ONE persistent kernel (288 CTAs, software grid barrier) runs the
//          whole GEMM DAG (powers || W-stack || V-stack, split-K slabs with
//          fixed z-order reduce), then k_assemble -> fp16 tap bank.
// Stage 2: mma.sync m16n8k16 fp16 conv; TM=256 per CTA, each warp 32t x 64o
//          (24 LDSM4 per 64 MMAs - tensor-bound), ldmatrix.x4 operands,
//          K taps via cp.async.bulk 4-stage mbarrier ring. fp32 accumulate.
// ---------------------------------------------------------------------------

#define SEQ   4096
#define BATCH 16
#define DIN   64
#define NST   512
#define DMAX  112
#define TM    256
#define VW    448

#define XSTRH 72            // X smem row stride (halves) -> 144 B
#define KSTRH 72
#define TAPH  4608
#define TAPB  9216
#define NSTG  4

#define SM_X    0
#define SM_K    52992       // 368*144
#define SM_BAR  89856       // 52992 + 4*9216
#define SM_TOTAL 89920

#define NCTA  288

// fp32 scratch
#define OFF_P2   0
#define OFF_P4   262144
#define OFF_P8   524288
#define OFF_P16  786432
#define OFF_P32  1048576
#define OFF_P64  1310720
#define OFF_W    1572864
#define OFF_V    2097152
#define OFF_S0   2326528
#define OFF_S1   3375104
#define SCRATCH_FLOATS 4423680
__device__ float g_scratch[SCRATCH_FLOATS];

// fp16 tap bank: g_K[d*TAPH + o*KSTRH + i]
__device__ __half g_K[DMAX * TAPH];

// grid barrier state
__device__ unsigned int g_arrive;
__device__ volatile unsigned int g_epoch;

// ---------------- PTX helpers ----------------
__device__ __forceinline__ uint32_t smem_u32(const void* p) {
    uint32_t a;
    asm("{ .reg .u64 t; cvta.to.shared.u64 t, %1; cvt.u32.u64 %0, t; }"
        : "=r"(a) : "l"(p));
    return a;
}
#define MBAR_INIT(addr, cnt) \
    asm volatile("mbarrier.init.shared.b64 [%0], %1;" :: "r"(addr), "r"(cnt) : "memory")
#define MBAR_EXPECT_TX(addr, bytes) \
    asm volatile("mbarrier.arrive.expect_tx.shared.b64 _, [%0], %1;" :: "r"(addr), "r"(bytes) : "memory")
#define MBAR_ARRIVE(addr) \
    asm volatile("mbarrier.arrive.release.cta.shared.b64 _, [%0];" :: "r"(addr) : "memory")
#define MBAR_WAIT(addr, par) do { \
    uint32_t _m = (addr), _p = (par), _d; \
    asm volatile("{\n\t.reg .pred p;\n\t" \
        "mbarrier.try_wait.parity.acquire.cta.shared::cta.b64 p, [%1], %2;\n\t" \
        "selp.b32 %0, 1, 0, p;\n\t}" : "=r"(_d) : "r"(_m), "r"(_p) : "memory"); \
    if (!_d) { \
        asm volatile("{\n\t.reg .pred P1;\n\t" \
            "WL_%=:\n\t" \
            "mbarrier.try_wait.parity.acquire.cta.shared::cta.b64 P1, [%0], %1, 0x989680;\n\t" \
            "@P1 bra.uni WD_%=;\n\t" \
            "bra.uni WL_%=;\n\t" \
            "WD_%=:\n\t}" :: "r"(_m), "r"(_p) : "memory"); \
    } \
} while (0)
__device__ __forceinline__ void bulk_g2s(uint32_t dst, const void* src,
                                         uint32_t bytes, uint32_t mbar) {
    asm volatile("cp.async.bulk.shared::cta.global.mbarrier::complete_tx::bytes "
        "[%0], [%1], %2, [%3];" :: "r"(dst), "l"(src), "r"(bytes), "r"(mbar) : "memory");
}
__device__ __forceinline__ void mma_f16(float* c, uint32_t a0, uint32_t a1,
                                        uint32_t a2, uint32_t a3,
                                        uint32_t b0, uint32_t b1) {
    asm volatile("mma.sync.aligned.m16n8k16.row.col.f32.f16.f16.f32 "
        "{%0,%1,%2,%3}, {%4,%5,%6,%7}, {%8,%9}, {%0,%1,%2,%3};"
        : "+f"(c[0]), "+f"(c[1]), "+f"(c[2]), "+f"(c[3])
        : "r"(a0), "r"(a1), "r"(a2), "r"(a3), "r"(b0), "r"(b1));
}
#define LDSM4(r0, r1, r2, r3, addr) \
    asm volatile("ldmatrix.sync.aligned.m8n8.x4.shared.b16 {%0,%1,%2,%3}, [%4];" \
        : "=r"(r0), "=r"(r1), "=r"(r2), "=r"(r3) : "r"(addr))
__device__ __forceinline__ uint32_t pack_h2(float a, float b) {
    __half2 t;
    t.x = __float2half_rn(a);
    t.y = __float2half_rn(b);
    return *(uint32_t*)&t;
}

// ---------------------------------------------------------------------------
// grid barrier (sense-reversing epoch; deterministic)
// ---------------------------------------------------------------------------
__device__ __noinline__ void gbar() {
    __syncthreads();
    if (threadIdx.x == 0) {
        __threadfence();
        unsigned int e = g_epoch;
        if (atomicAdd(&g_arrive, 1u) == NCTA - 1u) {
            g_arrive = 0u;
            __threadfence();
            atomicAdd((unsigned int*)&g_epoch, 1u);
        } else {
            while (g_epoch == e) __nanosleep(32);
        }
        __threadfence();
    }
    __syncthreads();
}

// ---------------------------------------------------------------------------
// 64x64 fp32 GEMM tile over K range [koff, koff+Kc)
// ---------------------------------------------------------------------------
__device__ __noinline__ void tileGemm(
    const float* __restrict__ A, const float* __restrict__ B,
    float* __restrict__ out, int ldo, int m0, int n0, int Kc, int koff,
    int lda, int ldb, float (*As)[68], float (*Bs)[68])
{
    const int tid = threadIdx.x;
    const int tn = tid & 15, tm = tid >> 4;
    const int la_m = (tid * 4) >> 4;
    const int la_k = (tid * 4) & 15;
    const int lb_k = (tid * 4) >> 6;
    const int lb_n = (tid * 4) & 63;
    float acc[4][4] = {};

    for (int k0 = koff; k0 < koff + Kc; k0 += 16) {
        float4 av = *(const float4*)(A + (size_t)(m0 + la_m) * lda + (k0 + la_k));
        As[la_k + 0][la_m] = av.x; As[la_k + 1][la_m] = av.y;
        As[la_k + 2][la_m] = av.z; As[la_k + 3][la_m] = av.w;
        float4 bv = *(const float4*)(B + (size_t)(k0 + lb_k) * ldb + (n0 + lb_n));
        *(float4*)&Bs[lb_k][lb_n] = bv;
        __syncthreads();
        #pragma unroll
        for (int kk = 0; kk < 16; kk++) {
            float4 a = *(const float4*)&As[kk][tm * 4];
            float4 b = *(const float4*)&Bs[kk][tn * 4];
            acc[0][0] += a.x * b.x; acc[0][1] += a.x * b.y; acc[0][2] += a.x * b.z; acc[0][3] += a.x * b.w;
            acc[1][0] += a.y * b.x; acc[1][1] += a.y * b.y; acc[1][2] += a.y * b.z; acc[1][3] += a.y * b.w;
            acc[2][0] += a.z * b.x; acc[2][1] += a.z * b.y; acc[2][2] += a.z * b.z; acc[2][3] += a.z * b.w;
            acc[3][0] += a.w * b.x; acc[3][1] += a.w * b.y; acc[3][2] += a.w * b.z; acc[3][3] += a.w * b.w;
        }
        __syncthreads();
    }
    #pragma unroll
    for (int r = 0; r < 4; r++) {
        float4 o = make_float4(acc[r][0], acc[r][1], acc[r][2], acc[r][3]);
        *(float4*)(out + (size_t)(m0 + tm * 4 + r) * ldo + (n0 + tn * 4)) = o;
    }
}

// ---------------------------------------------------------------------------
// fixed z-order slab reduction
// ---------------------------------------------------------------------------
__device__ __noinline__ void redAdd(
    const float* __restrict__ slab, float* __restrict__ dst,
    int ldd, int N, size_t zstride, int Z, int f4base, int f4cnt)
{
    const int fpr = N >> 2;
    for (int i = f4base + threadIdx.x; i < f4base + f4cnt; i += 256) {
        int r = i / fpr, c4 = (i - r * fpr) * 4;
        const float* sp = slab + (size_t)r * N + c4;
        float sx = 0.f, sy = 0.f, sz = 0.f, sw = 0.f;
        for (int z = 0; z < Z; z++) {
            float4 t = *(const float4*)(sp + zstride * z);
            sx += t.x; sy += t.y; sz += t.z; sw += t.w;
        }
        *(float4*)(dst + (size_t)r * ldd + c4) = make_float4(sx, sy, sz, sw);
    }
}

// ---------------------------------------------------------------------------
// K_d = W_{d&15} * V_{d>>4} (+D for d==0) -> fp16 bank g_K[d][o][i].
// ---------------------------------------------------------------------------
__device__ __noinline__ void kasm(int d, const float* __restrict__ Dm,
                                  float (*As)[68], float (*Bs)[68])
{
    const float* Wc = g_scratch + OFF_W;
    const float* Vc = g_scratch + OFF_V;
    const int d1 = d & 15, j = d >> 4;
    const float* A = Wc + (size_t)d1 * 64 * NST;
    const float* B = Vc + j * 64;

    const int tid = threadIdx.x;
    const int tn = tid & 15, tm = tid >> 4;
    const int la_m = (tid * 4) >> 4;
    const int la_k = (tid * 4) & 15;
    const int lb_k = (tid * 4) >> 6;
    const int lb_n = (tid * 4) & 63;
    float acc[4][4] = {};

    for (int k0 = 0; k0 < NST; k0 += 16) {
        float4 av = *(const float4*)(A + (size_t)la_m * NST + (k0 + la_k));
        As[la_k + 0][la_m] = av.x; As[la_k + 1][la_m] = av.y;
        As[la_k + 2][la_m] = av.z; As[la_k + 3][la_m] = av.w;
        float4 bv = *(const float4*)(B + (size_t)(k0 + lb_k) * VW + lb_n);
        *(float4*)&Bs[lb_k][lb_n] = bv;
        __syncthreads();
        #pragma unroll
        for (int kk = 0; kk < 16; kk++) {
            float4 a = *(const float4*)&As[kk][tm * 4];
            float4 b = *(const float4*)&Bs[kk][tn * 4];
            acc[0][0] += a.x * b.x; acc[0][1] += a.x * b.y; acc[0][2] += a.x * b.z; acc[0][3] += a.x * b.w;
            acc[1][0] += a.y * b.x; acc[1][1] += a.y * b.y; acc[1][2] += a.y * b.z; acc[1][3] += a.y * b.w;
            acc[2][0] += a.z * b.x; acc[2][1] += a.z * b.y; acc[2][2] += a.z * b.z; acc[2][3] += a.z * b.w;
            acc[3][0] += a.w * b.x; acc[3][1] += a.w * b.y; acc[3][2] += a.w * b.z; acc[3][3] += a.w * b.w;
        }
        __syncthreads();
    }
    __half* out = g_K + (size_t)d * TAPH;
    #pragma unroll
    for (int r = 0; r < 4; r++) {
        #pragma unroll
        for (int c = 0; c < 4; c++) {
            int o = tm * 4 + r, i = tn * 4 + c;
            float v = acc[r][c];
            if (d == 0) v += Dm[o * DIN + i];
            out[o * KSTRH + i] = __float2half_rn(v);
        }
    }
}

// ---------------------------------------------------------------------------
// Persistent stage-1 kernel
// ---------------------------------------------------------------------------
__global__ __launch_bounds__(256, 2) void stage1(const float* __restrict__ A,
                                                 const float* __restrict__ Dm)
{
    __shared__ float As[16][68];
    __shared__ float Bs[16][68];
    float* S   = g_scratch;
    float* P2  = S + OFF_P2;  float* P4  = S + OFF_P4;
    float* P8  = S + OFF_P8;  float* P16 = S + OFF_P16;
    float* P32 = S + OFF_P32; float* P64 = S + OFF_P64;
    float* W   = S + OFF_W;   float* V   = S + OFF_V;
    float* S0  = S + OFF_S0;  float* S1  = S + OFF_S1;
    const int bid = blockIdx.x;

    // G1: P2 = A*A (z=4) || W1 = C*A (z=4)
    if (bid < 256) {
        int t = bid & 63, z = bid >> 6;
        tileGemm(A, A, S0 + (size_t)z * 262144, 512, (t >> 3) * 64, (t & 7) * 64,
                 128, z * 128, 512, 512, As, Bs);
    } else {
        int t = bid - 256, ti = t & 7, z = t >> 3;
        tileGemm(W, A, S1 + (size_t)z * 32768, 512, 0, ti * 64,
                 128, z * 128, 512, 512, As, Bs);
    }
    gbar();
    if (bid < 256) redAdd(S0, P2, 512, 512, 262144, 4, bid * 256, 256);
    else           redAdd(S1, W + (size_t)64 * 512, 512, 512, 32768, 4, (bid - 256) * 256, 256);
    gbar();

    // G2: P4 = P2^2 (z=4) || W2 = W[0:128)*P2 (z=2)
    if (bid < 256) {
        int t = bid & 63, z = bid >> 6;
        tileGemm(P2, P2, S0 + (size_t)z * 262144, 512, (t >> 3) * 64, (t & 7) * 64,
                 128, z * 128, 512, 512, As, Bs);
    } else {
        int t = bid - 256, tile = t & 15, z = t >> 4;
        tileGemm(W, P2, S1 + (size_t)z * 65536, 512, (tile >> 3) * 64, (tile & 7) * 64,
                 256, z * 256, 512, 512, As, Bs);
    }
    gbar();
    if (bid < 256) redAdd(S0, P4, 512, 512, 262144, 4, bid * 256, 256);
    else           redAdd(S1, W + (size_t)128 * 512, 512, 512, 65536, 2, (bid - 256) * 512, 512);
    gbar();

    // G3: P8 = P4^2 (z=2, 128 CTAs) || W3 = W[0:256)*P4 (z=4, 128 CTAs)
    if (bid < 128) {
        int t = bid & 63, z = bid >> 6;
        tileGemm(P4, P4, S0 + (size_t)z * 262144, 512, (t >> 3) * 64, (t & 7) * 64,
                 256, z * 256, 512, 512, As, Bs);
    } else if (bid < 256) {
        int t = bid - 128, tile = t & 31, z = t >> 5;
        tileGemm(W, P4, S1 + (size_t)z * 131072, 512, (tile >> 3) * 64, (tile & 7) * 64,
                 128, z * 128, 512, 512, As, Bs);
    }
    gbar();
    if (bid < 128)      redAdd(S0, P8, 512, 512, 262144, 2, bid * 512, 512);
    else if (bid < 256) redAdd(S1, W + (size_t)256 * 512, 512, 512, 131072, 4, (bid - 128) * 256, 256);
    gbar();

    // G4: P16 = P8^2 (z=2, 128 CTAs) || W4 = W[0:512)*P8 (z=2, 128 CTAs)
    if (bid < 128) {
        int t = bid & 63, z = bid >> 6;
        tileGemm(P8, P8, S0 + (size_t)z * 262144, 512, (t >> 3) * 64, (t & 7) * 64,
                 256, z * 256, 512, 512, As, Bs);
    } else if (bid < 256) {
        int t = bid - 128, tile = t & 63, z = t >> 6;
        tileGemm(W, P8, S1 + (size_t)z * 262144, 512, (tile >> 3) * 64, (tile & 7) * 64,
                 256, z * 256, 512, 512, As, Bs);
    }
    gbar();
    if (bid < 128)      redAdd(S0, P16, 512, 512, 262144, 2, bid * 512, 512);
    else if (bid < 256) redAdd(S1, W + (size_t)512 * 512, 512, 512, 262144, 2, (bid - 128) * 512, 512);
    gbar();

    // G5: P32 = P16^2 (z=4) || V1 = P16*V0 (z=4)
    if (bid < 256) {
        int t = bid & 63, z = bid >> 6;
        tileGemm(P16, P16, S0 + (size_t)z * 262144, 512, (t >> 3) * 64, (t & 7) * 64,
                 128, z * 128, 512, 512, As, Bs);
    } else {
        int t = bid - 256, ti = t & 7, z = t >> 3;
        tileGemm(P16, V, S1 + (size_t)z * 32768, 64, ti * 64, 0,
                 128, z * 128, 512, VW, As, Bs);
    }
    gbar();
    if (bid < 256) redAdd(S0, P32, 512, 512, 262144, 4, bid * 256, 256);
    else           redAdd(S1, V + 64, VW, 64, 32768, 4, (bid - 256) * 256, 256);
    gbar();

    // G6: P64 = P32^2 (z=4) || V23 = P32*V[0:128) (z=2)
    if (bid < 256) {
        int t = bid & 63, z = bid >> 6;
        tileGemm(P32, P32, S0 + (size_t)z * 262144, 512, (t >> 3) * 64, (t & 7) * 64,
                 128, z * 128, 512, 512, As, Bs);
    } else {
        int t = bid - 256, tile = t & 15, z = t >> 4;
        tileGemm(P32, V, S1 + (size_t)z * 65536, 128, (tile >> 1) * 64, (tile & 1) * 64,
                 256, z * 256, 512, VW, As, Bs);
    }
    gbar();
    if (bid < 256) redAdd(S0, P64, 512, 512, 262144, 4, bid * 256, 256);
    else           redAdd(S1, V + 128, VW, 128, 65536, 2, (bid - 256) * 512, 512);
    gbar();

    // G7: V456 = P64*V[0:192) (z=8, 192 CTAs)
    if (bid < 192) {
        int z = bid / 24, tile = bid % 24;
        tileGemm(P64, V, S0 + (size_t)z * 98304, 192, (tile / 3) * 64, (tile % 3) * 64,
                 64, z * 64, 512, VW, As, Bs);
    }
    gbar();
    if (bid < 192) redAdd(S0, V + 256, VW, 192, 98304, 8, bid * 128, 128);
    gbar();

    // G8: tap bank
    if (bid < DMAX) kasm(bid, Dm, As, Bs);
}

// ---------------------------------------------------------------------------
// fp16 mma.sync conv: TM=256, 8 warps x (32t x 64o), ldmatrix.x4 operands.
// ---------------------------------------------------------------------------
__global__ __launch_bounds__(256, 2) void conv_tc(const float* __restrict__ x,
                                                  float* __restrict__ y)
{
    extern __shared__ char sm[];
    __half* Xs = (__half*)(sm + SM_X);
    const uint32_t sb = smem_u32(sm);
    const uint32_t barF = sb + SM_BAR;
    const uint32_t barE = sb + SM_BAR + 32;
    const int tid = threadIdx.x;
    const int wid = tid >> 5, lane = tid & 31;
    const int gid = lane >> 2, tig = lane & 3;
    const int b = blockIdx.y;
    const int t0 = blockIdx.x * TM;

    if (tid == 0) {
        #pragma unroll
        for (int s = 0; s < NSTG; s++) {
            MBAR_INIT(barF + s * 8, 1);
            MBAR_INIT(barE + s * 8, 8);
        }
    }
    __syncthreads();

    if (tid == 0) {
        #pragma unroll
        for (int s = 0; s < NSTG; s++) {
            MBAR_EXPECT_TX(barF + s * 8, TAPB);
            bulk_g2s(sb + SM_K + s * TAPB, g_K + (size_t)s * TAPH, TAPB, barF + s * 8);
        }
    }

    // stage X window fp16: row u <-> global t = t0 - 111 + u, u in [0,367)
    for (int u = tid; u < TM + DMAX - 1; u += 256) {
        int tg = t0 - (DMAX - 1) + u;
        uint32_t* dst = (uint32_t*)(Xs + u * XSTRH);
        if (tg >= 0) {
            const float4* src = (const float4*)(x + ((size_t)b * SEQ + tg) * DIN);
            #pragma unroll
            for (int c = 0; c < 16; c += 2) {
                float4 v0 = src[c], v1 = src[c + 1];
                uint4 h;
                h.x = pack_h2(v0.x, v0.y); h.y = pack_h2(v0.z, v0.w);
                h.z = pack_h2(v1.x, v1.y); h.w = pack_h2(v1.z, v1.w);
                *(uint4*)(dst + c * 2) = h;
            }
        } else {
            #pragma unroll
            for (int c = 0; c < 8; c++)
                *(uint4*)(dst + c * 4) = make_uint4(0, 0, 0, 0);
        }
    }
    __syncthreads();

    float acc[16][4];
    #pragma unroll
    for (int nf = 0; nf < 16; nf++) {
        acc[nf][0] = 0.f; acc[nf][1] = 0.f; acc[nf][2] = 0.f; acc[nf][3] = 0.f;
    }

    // ldmatrix per-lane address invariants (byte offsets; row stride 144B)
    const uint32_t invA = (uint32_t)(wid * 32 + (lane & 15)) * 144u
                        + (uint32_t)(lane >> 4) * 16u;
    const uint32_t invB = (uint32_t)((lane & 7) + ((lane >> 4) << 3)) * 144u
                        + (uint32_t)((lane >> 3) & 1) * 16u;

    for (int d = 0; d < DMAX; d++) {
        const int s = d & 3;
        const uint32_t par = (d >> 2) & 1;
        MBAR_WAIT(barF + s * 8, par);

        const uint32_t aBase = sb + SM_X + invA + (uint32_t)(DMAX - 1 - d) * 144u;
        const uint32_t bBase = sb + SM_K + (uint32_t)s * TAPB + invB;

        #pragma unroll
        for (int kc = 0; kc < 4; kc++) {
            uint32_t a0, a1, a2, a3, a4, a5, a6, a7;
            LDSM4(a0, a1, a2, a3, aBase + kc * 32);            // rows [w*32, +16)
            LDSM4(a4, a5, a6, a7, aBase + 2304 + kc * 32);     // rows [w*32+16, +16)
            #pragma unroll
            for (int nfp = 0; nfp < 4; nfp++) {
                uint32_t b0, b1, b2, b3;
                LDSM4(b0, b1, b2, b3, bBase + nfp * 2304 + kc * 32);
                mma_f16(acc[2 * nfp],         a0, a1, a2, a3, b0, b1);
                mma_f16(acc[2 * nfp + 1],     a0, a1, a2, a3, b2, b3);
                mma_f16(acc[8 + 2 * nfp],     a4, a5, a6, a7, b0, b1);
                mma_f16(acc[8 + 2 * nfp + 1], a4, a5, a6, a7, b2, b3);
            }
        }

        if (lane == 0) MBAR_ARRIVE(barE + s * 8);
        if (tid == 0 && d + NSTG < DMAX) {
            MBAR_WAIT(barE + s * 8, par);
            MBAR_EXPECT_TX(barF + s * 8, TAPB);
            bulk_g2s(sb + SM_K + s * TAPB, g_K + (size_t)(d + NSTG) * TAPH, TAPB,
                     barF + s * 8);
        }
    }

    // epilogue: rowset0 -> rows gid, gid+8; rowset1 -> rows gid+16, gid+24
    const int r0 = t0 + wid * 32 + gid;
    #pragma unroll
    for (int nf = 0; nf < 8; nf++) {
        int col = nf * 8 + 2 * tig;
        *(float2*)(y + ((size_t)b * SEQ + r0) * DIN + col) =
            make_float2(acc[nf][0], acc[nf][1]);
        *(float2*)(y + ((size_t)b * SEQ + r0 + 8) * DIN + col) =
            make_float2(acc[nf][2], acc[nf][3]);
        *(float2*)(y + ((size_t)b * SEQ + r0 + 16) * DIN + col) =
            make_float2(acc[8 + nf][0], acc[8 + nf][1]);
        *(float2*)(y + ((size_t)b * SEQ + r0 + 24) * DIN + col) =
            make_float2(acc[8 + nf][2], acc[8 + nf][3]);
    }
}

// ---------------------------------------------------------------------------
extern "C" void kernel_launch(void* const* d_in, const int* in_sizes, int n_in,
                              void* d_out, int out_size)
{
    const float* x  = (const float*)d_in[0];
    const float* A  = (const float*)d_in[1];
    const float* Bm = (const float*)d_in[2];
    const float* Cm = (const float*)d_in[3];
    const float* Dm = (const float*)d_in[4];
    float* y = (float*)d_out;

    float* s = nullptr;
    cudaGetSymbolAddress((void**)&s, g_scratch);
    float* W = s + OFF_W;
    float* V = s + OFF_V;

    cudaFuncSetAttribute(conv_tc, cudaFuncAttributeMaxDynamicSharedMemorySize, SM_TOTAL);

    // seed W row-block 0 <- C ; V col-block 0 <- B
    cudaMemcpyAsync(W, Cm, (size_t)64 * NST * sizeof(float), cudaMemcpyDeviceToDevice);
    cudaMemcpy2DAsync(V, VW * sizeof(float), Bm, 64 * sizeof(float),
                      64 * sizeof(float), NST, cudaMemcpyDeviceToDevice);

    // whole stage 1 in one persistent launch
    stage1<<<NCTA, 256>>>(A, Dm);

    // tensor-core convolution (TM=256, warp tile 32t x 64o)
    conv_tc<<<dim3(SEQ / TM, BATCH), 256, SM_TOTAL>>>(x, y);
}

// round 11
// speedup vs baseline: 1.3744x; 1.0703x over previous
#include <cuda_runtime.h>
#include <cuda_fp16.h>
#include <cstdint>

// ---------------------------------------------------------------------------
// Linear SSM as truncated causal conv: y[t] = sum_{d<112} K_d x[t-d], K_0+=D.
// Stage 1: ONE persistent kernel (288 CTAs, software grid barrier) runs the
//          whole GEMM DAG (powers || W-stack || V-stack, split-K slabs with
//          fixed z-order reduce), then k_assemble -> fp16 tap bank.
//          GEMM cores use register prefetch (double-buffered global loads)
//          to overlap load latency with FFMA compute.
// Stage 2: mma.sync m16n8k16 fp16 conv; TM=256 per CTA, each warp 32t x 64o,
//          ldmatrix.x4 operands, K taps via cp.async.bulk 4-stage ring.
// ---------------------------------------------------------------------------

#define SEQ   4096
#define BATCH 16
#define DIN   64
#define NST   512
#define DMAX  112
#define TM    256
#define VW    448

#define XSTRH 72
#define KSTRH 72
#define TAPH  4608
#define TAPB  9216
#define NSTG  4

#define SM_X    0
#define SM_K    52992
#define SM_BAR  89856
#define SM_TOTAL 89920

#define NCTA  288

// fp32 scratch
#define OFF_P2   0
#define OFF_P4   262144
#define OFF_P8   524288
#define OFF_P16  786432
#define OFF_P32  1048576
#define OFF_P64  1310720
#define OFF_W    1572864
#define OFF_V    2097152
#define OFF_S0   2326528
#define OFF_S1   3375104
#define SCRATCH_FLOATS 4423680
__device__ float g_scratch[SCRATCH_FLOATS];

// fp16 tap bank: g_K[d*TAPH + o*KSTRH + i]
__device__ __half g_K[DMAX * TAPH];

// grid barrier state
__device__ unsigned int g_arrive;
__device__ volatile unsigned int g_epoch;

// ---------------- PTX helpers ----------------
__device__ __forceinline__ uint32_t smem_u32(const void* p) {
    uint32_t a;
    asm("{ .reg .u64 t; cvta.to.shared.u64 t, %1; cvt.u32.u64 %0, t; }"
        : "=r"(a) : "l"(p));
    return a;
}
#define MBAR_INIT(addr, cnt) \
    asm volatile("mbarrier.init.shared.b64 [%0], %1;" :: "r"(addr), "r"(cnt) : "memory")
#define MBAR_EXPECT_TX(addr, bytes) \
    asm volatile("mbarrier.arrive.expect_tx.shared.b64 _, [%0], %1;" :: "r"(addr), "r"(bytes) : "memory")
#define MBAR_ARRIVE(addr) \
    asm volatile("mbarrier.arrive.release.cta.shared.b64 _, [%0];" :: "r"(addr) : "memory")
#define MBAR_WAIT(addr, par) do { \
    uint32_t _m = (addr), _p = (par), _d; \
    asm volatile("{\n\t.reg .pred p;\n\t" \
        "mbarrier.try_wait.parity.acquire.cta.shared::cta.b64 p, [%1], %2;\n\t" \
        "selp.b32 %0, 1, 0, p;\n\t}" : "=r"(_d) : "r"(_m), "r"(_p) : "memory"); \
    if (!_d) { \
        asm volatile("{\n\t.reg .pred P1;\n\t" \
            "WL_%=:\n\t" \
            "mbarrier.try_wait.parity.acquire.cta.shared::cta.b64 P1, [%0], %1, 0x989680;\n\t" \
            "@P1 bra.uni WD_%=;\n\t" \
            "bra.uni WL_%=;\n\t" \
            "WD_%=:\n\t}" :: "r"(_m), "r"(_p) : "memory"); \
    } \
} while (0)
__device__ __forceinline__ void bulk_g2s(uint32_t dst, const void* src,
                                         uint32_t bytes, uint32_t mbar) {
    asm volatile("cp.async.bulk.shared::cta.global.mbarrier::complete_tx::bytes "
        "[%0], [%1], %2, [%3];" :: "r"(dst), "l"(src), "r"(bytes), "r"(mbar) : "memory");
}
__device__ __forceinline__ void mma_f16(float* c, uint32_t a0, uint32_t a1,
                                        uint32_t a2, uint32_t a3,
                                        uint32_t b0, uint32_t b1) {
    asm volatile("mma.sync.aligned.m16n8k16.row.col.f32.f16.f16.f32 "
        "{%0,%1,%2,%3}, {%4,%5,%6,%7}, {%8,%9}, {%0,%1,%2,%3};"
        : "+f"(c[0]), "+f"(c[1]), "+f"(c[2]), "+f"(c[3])
        : "r"(a0), "r"(a1), "r"(a2), "r"(a3), "r"(b0), "r"(b1));
}
#define LDSM4(r0, r1, r2, r3, addr) \
    asm volatile("ldmatrix.sync.aligned.m8n8.x4.shared.b16 {%0,%1,%2,%3}, [%4];" \
        : "=r"(r0), "=r"(r1), "=r"(r2), "=r"(r3) : "r"(addr))
__device__ __forceinline__ uint32_t pack_h2(float a, float b) {
    __half2 t;
    t.x = __float2half_rn(a);
    t.y = __float2half_rn(b);
    return *(uint32_t*)&t;
}

// ---------------------------------------------------------------------------
// grid barrier (sense-reversing epoch; deterministic)
// ---------------------------------------------------------------------------
__device__ __noinline__ void gbar() {
    __syncthreads();
    if (threadIdx.x == 0) {
        __threadfence();
        unsigned int e = g_epoch;
        if (atomicAdd(&g_arrive, 1u) == NCTA - 1u) {
            g_arrive = 0u;
            __threadfence();
            atomicAdd((unsigned int*)&g_epoch, 1u);
        } else {
            while (g_epoch == e) __nanosleep(32);
        }
        __threadfence();
    }
    __syncthreads();
}

// ---------------------------------------------------------------------------
// 64x64 fp32 GEMM tile over K range [koff, koff+Kc), global-load prefetch.
// ---------------------------------------------------------------------------
__device__ __noinline__ void tileGemm(
    const float* __restrict__ A, const float* __restrict__ B,
    float* __restrict__ out, int ldo, int m0, int n0, int Kc, int koff,
    int lda, int ldb, float (*As)[68], float (*Bs)[68])
{
    const int tid = threadIdx.x;
    const int tn = tid & 15, tm = tid >> 4;
    const int la_m = (tid * 4) >> 4;
    const int la_k = (tid * 4) & 15;
    const int lb_k = (tid * 4) >> 6;
    const int lb_n = (tid * 4) & 63;
    float acc[4][4] = {};

    const float* ap = A + (size_t)(m0 + la_m) * lda + (koff + la_k);
    const float* bp = B + (size_t)(koff + lb_k) * ldb + (n0 + lb_n);
    float4 av = *(const float4*)ap;
    float4 bv = *(const float4*)bp;

    for (int k0 = koff; k0 < koff + Kc; k0 += 16) {
        As[la_k + 0][la_m] = av.x; As[la_k + 1][la_m] = av.y;
        As[la_k + 2][la_m] = av.z; As[la_k + 3][la_m] = av.w;
        *(float4*)&Bs[lb_k][lb_n] = bv;
        __syncthreads();
        if (k0 + 16 < koff + Kc) {           // prefetch next chunk into regs
            ap += 16; bp += (size_t)16 * ldb;
            av = *(const float4*)ap;
            bv = *(const float4*)bp;
        }
        #pragma unroll
        for (int kk = 0; kk < 16; kk++) {
            float4 a = *(const float4*)&As[kk][tm * 4];
            float4 b = *(const float4*)&Bs[kk][tn * 4];
            acc[0][0] += a.x * b.x; acc[0][1] += a.x * b.y; acc[0][2] += a.x * b.z; acc[0][3] += a.x * b.w;
            acc[1][0] += a.y * b.x; acc[1][1] += a.y * b.y; acc[1][2] += a.y * b.z; acc[1][3] += a.y * b.w;
            acc[2][0] += a.z * b.x; acc[2][1] += a.z * b.y; acc[2][2] += a.z * b.z; acc[2][3] += a.z * b.w;
            acc[3][0] += a.w * b.x; acc[3][1] += a.w * b.y; acc[3][2] += a.w * b.z; acc[3][3] += a.w * b.w;
        }
        __syncthreads();
    }
    #pragma unroll
    for (int r = 0; r < 4; r++) {
        float4 o = make_float4(acc[r][0], acc[r][1], acc[r][2], acc[r][3]);
        *(float4*)(out + (size_t)(m0 + tm * 4 + r) * ldo + (n0 + tn * 4)) = o;
    }
}

// ---------------------------------------------------------------------------
// fixed z-order slab reduction
// ---------------------------------------------------------------------------
__device__ __noinline__ void redAdd(
    const float* __restrict__ slab, float* __restrict__ dst,
    int ldd, int N, size_t zstride, int Z, int f4base, int f4cnt)
{
    const int fpr = N >> 2;
    for (int i = f4base + threadIdx.x; i < f4base + f4cnt; i += 256) {
        int r = i / fpr, c4 = (i - r * fpr) * 4;
        const float* sp = slab + (size_t)r * N + c4;
        float sx = 0.f, sy = 0.f, sz = 0.f, sw = 0.f;
        for (int z = 0; z < Z; z++) {
            float4 t = *(const float4*)(sp + zstride * z);
            sx += t.x; sy += t.y; sz += t.z; sw += t.w;
        }
        *(float4*)(dst + (size_t)r * ldd + c4) = make_float4(sx, sy, sz, sw);
    }
}

// ---------------------------------------------------------------------------
// K_d = W_{d&15} * V_{d>>4} (+D for d==0) -> fp16 bank, prefetched loads.
// ---------------------------------------------------------------------------
__device__ __noinline__ void kasm(int d, const float* __restrict__ Dm,
                                  float (*As)[68], float (*Bs)[68])
{
    const float* Wc = g_scratch + OFF_W;
    const float* Vc = g_scratch + OFF_V;
    const int d1 = d & 15, j = d >> 4;
    const float* A = Wc + (size_t)d1 * 64 * NST;
    const float* B = Vc + j * 64;

    const int tid = threadIdx.x;
    const int tn = tid & 15, tm = tid >> 4;
    const int la_m = (tid * 4) >> 4;
    const int la_k = (tid * 4) & 15;
    const int lb_k = (tid * 4) >> 6;
    const int lb_n = (tid * 4) & 63;
    float acc[4][4] = {};

    const float* ap = A + (size_t)la_m * NST + la_k;
    const float* bp = B + (size_t)lb_k * VW + lb_n;
    float4 av = *(const float4*)ap;
    float4 bv = *(const float4*)bp;

    for (int k0 = 0; k0 < NST; k0 += 16) {
        As[la_k + 0][la_m] = av.x; As[la_k + 1][la_m] = av.y;
        As[la_k + 2][la_m] = av.z; As[la_k + 3][la_m] = av.w;
        *(float4*)&Bs[lb_k][lb_n] = bv;
        __syncthreads();
        if (k0 + 16 < NST) {
            ap += 16; bp += (size_t)16 * VW;
            av = *(const float4*)ap;
            bv = *(const float4*)bp;
        }
        #pragma unroll
        for (int kk = 0; kk < 16; kk++) {
            float4 a = *(const float4*)&As[kk][tm * 4];
            float4 b = *(const float4*)&Bs[kk][tn * 4];
            acc[0][0] += a.x * b.x; acc[0][1] += a.x * b.y; acc[0][2] += a.x * b.z; acc[0][3] += a.x * b.w;
            acc[1][0] += a.y * b.x; acc[1][1] += a.y * b.y; acc[1][2] += a.y * b.z; acc[1][3] += a.y * b.w;
            acc[2][0] += a.z * b.x; acc[2][1] += a.z * b.y; acc[2][2] += a.z * b.z; acc[2][3] += a.z * b.w;
            acc[3][0] += a.w * b.x; acc[3][1] += a.w * b.y; acc[3][2] += a.w * b.z; acc[3][3] += a.w * b.w;
        }
        __syncthreads();
    }
    __half* out = g_K + (size_t)d * TAPH;
    #pragma unroll
    for (int r = 0; r < 4; r++) {
        #pragma unroll
        for (int c = 0; c < 4; c++) {
            int o = tm * 4 + r, i = tn * 4 + c;
            float v = acc[r][c];
            if (d == 0) v += Dm[o * DIN + i];
            out[o * KSTRH + i] = __float2half_rn(v);
        }
    }
}

// ---------------------------------------------------------------------------
// Persistent stage-1 kernel
// ---------------------------------------------------------------------------
__global__ __launch_bounds__(256, 2) void stage1(const float* __restrict__ A,
                                                 const float* __restrict__ Dm)
{
    __shared__ float As[16][68];
    __shared__ float Bs[16][68];
    float* S   = g_scratch;
    float* P2  = S + OFF_P2;  float* P4  = S + OFF_P4;
    float* P8  = S + OFF_P8;  float* P16 = S + OFF_P16;
    float* P32 = S + OFF_P32; float* P64 = S + OFF_P64;
    float* W   = S + OFF_W;   float* V   = S + OFF_V;
    float* S0  = S + OFF_S0;  float* S1  = S + OFF_S1;
    const int bid = blockIdx.x;

    // G1: P2 = A*A (z=4) || W1 = C*A (z=4)
    if (bid < 256) {
        int t = bid & 63, z = bid >> 6;
        tileGemm(A, A, S0 + (size_t)z * 262144, 512, (t >> 3) * 64, (t & 7) * 64,
                 128, z * 128, 512, 512, As, Bs);
    } else {
        int t = bid - 256, ti = t & 7, z = t >> 3;
        tileGemm(W, A, S1 + (size_t)z * 32768, 512, 0, ti * 64,
                 128, z * 128, 512, 512, As, Bs);
    }
    gbar();
    if (bid < 256) redAdd(S0, P2, 512, 512, 262144, 4, bid * 256, 256);
    else           redAdd(S1, W + (size_t)64 * 512, 512, 512, 32768, 4, (bid - 256) * 256, 256);
    gbar();

    // G2: P4 = P2^2 (z=4) || W2 = W[0:128)*P2 (z=2)
    if (bid < 256) {
        int t = bid & 63, z = bid >> 6;
        tileGemm(P2, P2, S0 + (size_t)z * 262144, 512, (t >> 3) * 64, (t & 7) * 64,
                 128, z * 128, 512, 512, As, Bs);
    } else {
        int t = bid - 256, tile = t & 15, z = t >> 4;
        tileGemm(W, P2, S1 + (size_t)z * 65536, 512, (tile >> 3) * 64, (tile & 7) * 64,
                 256, z * 256, 512, 512, As, Bs);
    }
    gbar();
    if (bid < 256) redAdd(S0, P4, 512, 512, 262144, 4, bid * 256, 256);
    else           redAdd(S1, W + (size_t)128 * 512, 512, 512, 65536, 2, (bid - 256) * 512, 512);
    gbar();

    // G3: P8 = P4^2 (z=2, 128 CTAs) || W3 = W[0:256)*P4 (z=4, 128 CTAs)
    if (bid < 128) {
        int t = bid & 63, z = bid >> 6;
        tileGemm(P4, P4, S0 + (size_t)z * 262144, 512, (t >> 3) * 64, (t & 7) * 64,
                 256, z * 256, 512, 512, As, Bs);
    } else if (bid < 256) {
        int t = bid - 128, tile = t & 31, z = t >> 5;
        tileGemm(W, P4, S1 + (size_t)z * 131072, 512, (tile >> 3) * 64, (tile & 7) * 64,
                 128, z * 128, 512, 512, As, Bs);
    }
    gbar();
    if (bid < 128)      redAdd(S0, P8, 512, 512, 262144, 2, bid * 512, 512);
    else if (bid < 256) redAdd(S1, W + (size_t)256 * 512, 512, 512, 131072, 4, (bid - 128) * 256, 256);
    gbar();

    // G4: P16 = P8^2 (z=2, 128 CTAs) || W4 = W[0:512)*P8 (z=2, 128 CTAs)
    if (bid < 128) {
        int t = bid & 63, z = bid >> 6;
        tileGemm(P8, P8, S0 + (size_t)z * 262144, 512, (t >> 3) * 64, (t & 7) * 64,
                 256, z * 256, 512, 512, As, Bs);
    } else if (bid < 256) {
        int t = bid - 128, tile = t & 63, z = t >> 6;
        tileGemm(W, P8, S1 + (size_t)z * 262144, 512, (tile >> 3) * 64, (tile & 7) * 64,
                 256, z * 256, 512, 512, As, Bs);
    }
    gbar();
    if (bid < 128)      redAdd(S0, P16, 512, 512, 262144, 2, bid * 512, 512);
    else if (bid < 256) redAdd(S1, W + (size_t)512 * 512, 512, 512, 262144, 2, (bid - 128) * 512, 512);
    gbar();

    // G5: P32 = P16^2 (z=4) || V1 = P16*V0 (z=4)
    if (bid < 256) {
        int t = bid & 63, z = bid >> 6;
        tileGemm(P16, P16, S0 + (size_t)z * 262144, 512, (t >> 3) * 64, (t & 7) * 64,
                 128, z * 128, 512, 512, As, Bs);
    } else {
        int t = bid - 256, ti = t & 7, z = t >> 3;
        tileGemm(P16, V, S1 + (size_t)z * 32768, 64, ti * 64, 0,
                 128, z * 128, 512, VW, As, Bs);
    }
    gbar();
    if (bid < 256) redAdd(S0, P32, 512, 512, 262144, 4, bid * 256, 256);
    else           redAdd(S1, V + 64, VW, 64, 32768, 4, (bid - 256) * 256, 256);
    gbar();

    // G6: P64 = P32^2 (z=4) || V23 = P32*V[0:128) (z=2)
    if (bid < 256) {
        int t = bid & 63, z = bid >> 6;
        tileGemm(P32, P32, S0 + (size_t)z * 262144, 512, (t >> 3) * 64, (t & 7) * 64,
                 128, z * 128, 512, 512, As, Bs);
    } else {
        int t = bid - 256, tile = t & 15, z = t >> 4;
        tileGemm(P32, V, S1 + (size_t)z * 65536, 128, (tile >> 1) * 64, (tile & 1) * 64,
                 256, z * 256, 512, VW, As, Bs);
    }
    gbar();
    if (bid < 256) redAdd(S0, P64, 512, 512, 262144, 4, bid * 256, 256);
    else           redAdd(S1, V + 128, VW, 128, 65536, 2, (bid - 256) * 512, 512);
    gbar();

    // G7: V456 = P64*V[0:192) (z=8, 192 CTAs)
    if (bid < 192) {
        int z = bid / 24, tile = bid % 24;
        tileGemm(P64, V, S0 + (size_t)z * 98304, 192, (tile / 3) * 64, (tile % 3) * 64,
                 64, z * 64, 512, VW, As, Bs);
    }
    gbar();
    if (bid < 192) redAdd(S0, V + 256, VW, 192, 98304, 8, bid * 128, 128);
    gbar();

    // G8: tap bank
    if (bid < DMAX) kasm(bid, Dm, As, Bs);
}

// ---------------------------------------------------------------------------
// fp16 mma.sync conv: TM=256, 8 warps x (32t x 64o), ldmatrix.x4 operands.
// (unchanged from round 9 - validated at 138.8us, tensor 70.9%)
// ---------------------------------------------------------------------------
__global__ __launch_bounds__(256, 2) void conv_tc(const float* __restrict__ x,
                                                  float* __restrict__ y)
{
    extern __shared__ char sm[];
    __half* Xs = (__half*)(sm + SM_X);
    const uint32_t sb = smem_u32(sm);
    const uint32_t barF = sb + SM_BAR;
    const uint32_t barE = sb + SM_BAR + 32;
    const int tid = threadIdx.x;
    const int wid = tid >> 5, lane = tid & 31;
    const int gid = lane >> 2, tig = lane & 3;
    const int b = blockIdx.y;
    const int t0 = blockIdx.x * TM;

    if (tid == 0) {
        #pragma unroll
        for (int s = 0; s < NSTG; s++) {
            MBAR_INIT(barF + s * 8, 1);
            MBAR_INIT(barE + s * 8, 8);
        }
    }
    __syncthreads();

    if (tid == 0) {
        #pragma unroll
        for (int s = 0; s < NSTG; s++) {
            MBAR_EXPECT_TX(barF + s * 8, TAPB);
            bulk_g2s(sb + SM_K + s * TAPB, g_K + (size_t)s * TAPH, TAPB, barF + s * 8);
        }
    }

    for (int u = tid; u < TM + DMAX - 1; u += 256) {
        int tg = t0 - (DMAX - 1) + u;
        uint32_t* dst = (uint32_t*)(Xs + u * XSTRH);
        if (tg >= 0) {
            const float4* src = (const float4*)(x + ((size_t)b * SEQ + tg) * DIN);
            #pragma unroll
            for (int c = 0; c < 16; c += 2) {
                float4 v0 = src[c], v1 = src[c + 1];
                uint4 h;
                h.x = pack_h2(v0.x, v0.y); h.y = pack_h2(v0.z, v0.w);
                h.z = pack_h2(v1.x, v1.y); h.w = pack_h2(v1.z, v1.w);
                *(uint4*)(dst + c * 2) = h;
            }
        } else {
            #pragma unroll
            for (int c = 0; c < 8; c++)
                *(uint4*)(dst + c * 4) = make_uint4(0, 0, 0, 0);
        }
    }
    __syncthreads();

    float acc[16][4];
    #pragma unroll
    for (int nf = 0; nf < 16; nf++) {
        acc[nf][0] = 0.f; acc[nf][1] = 0.f; acc[nf][2] = 0.f; acc[nf][3] = 0.f;
    }

    const uint32_t invA = (uint32_t)(wid * 32 + (lane & 15)) * 144u
                        + (uint32_t)(lane >> 4) * 16u;
    const uint32_t invB = (uint32_t)((lane & 7) + ((lane >> 4) << 3)) * 144u
                        + (uint32_t)((lane >> 3) & 1) * 16u;

    for (int d = 0; d < DMAX; d++) {
        const int s = d & 3;
        const uint32_t par = (d >> 2) & 1;
        MBAR_WAIT(barF + s * 8, par);

        const uint32_t aBase = sb + SM_X + invA + (uint32_t)(DMAX - 1 - d) * 144u;
        const uint32_t bBase = sb + SM_K + (uint32_t)s * TAPB + invB;

        #pragma unroll
        for (int kc = 0; kc < 4; kc++) {
            uint32_t a0, a1, a2, a3, a4, a5, a6, a7;
            LDSM4(a0, a1, a2, a3, aBase + kc * 32);
            LDSM4(a4, a5, a6, a7, aBase + 2304 + kc * 32);
            #pragma unroll
            for (int nfp = 0; nfp < 4; nfp++) {
                uint32_t b0, b1, b2, b3;
                LDSM4(b0, b1, b2, b3, bBase + nfp * 2304 + kc * 32);
                mma_f16(acc[2 * nfp],         a0, a1, a2, a3, b0, b1);
                mma_f16(acc[2 * nfp + 1],     a0, a1, a2, a3, b2, b3);
                mma_f16(acc[8 + 2 * nfp],     a4, a5, a6, a7, b0, b1);
                mma_f16(acc[8 + 2 * nfp + 1], a4, a5, a6, a7, b2, b3);
            }
        }

        if (lane == 0) MBAR_ARRIVE(barE + s * 8);
        if (tid == 0 && d + NSTG < DMAX) {
            MBAR_WAIT(barE + s * 8, par);
            MBAR_EXPECT_TX(barF + s * 8, TAPB);
            bulk_g2s(sb + SM_K + s * TAPB, g_K + (size_t)(d + NSTG) * TAPH, TAPB,
                     barF + s * 8);
        }
    }

    const int r0 = t0 + wid * 32 + gid;
    #pragma unroll
    for (int nf = 0; nf < 8; nf++) {
        int col = nf * 8 + 2 * tig;
        *(float2*)(y + ((size_t)b * SEQ + r0) * DIN + col) =
            make_float2(acc[nf][0], acc[nf][1]);
        *(float2*)(y + ((size_t)b * SEQ + r0 + 8) * DIN + col) =
            make_float2(acc[nf][2], acc[nf][3]);
        *(float2*)(y + ((size_t)b * SEQ + r0 + 16) * DIN + col) =
            make_float2(acc[8 + nf][0], acc[8 + nf][1]);
        *(float2*)(y + ((size_t)b * SEQ + r0 + 24) * DIN + col) =
            make_float2(acc[8 + nf][2], acc[8 + nf][3]);
    }
}

// ---------------------------------------------------------------------------
extern "C" void kernel_launch(void* const* d_in, const int* in_sizes, int n_in,
                              void* d_out, int out_size)
{
    const float* x  = (const float*)d_in[0];
    const float* A  = (const float*)d_in[1];
    const float* Bm = (const float*)d_in[2];
    const float* Cm = (const float*)d_in[3];
    const float* Dm = (const float*)d_in[4];
    float* y = (float*)d_out;

    float* s = nullptr;
    cudaGetSymbolAddress((void**)&s, g_scratch);
    float* W = s + OFF_W;
    float* V = s + OFF_V;

    cudaFuncSetAttribute(conv_tc, cudaFuncAttributeMaxDynamicSharedMemorySize, SM_TOTAL);

    // seed W row-block 0 <- C ; V col-block 0 <- B
    cudaMemcpyAsync(W, Cm, (size_t)64 * NST * sizeof(float), cudaMemcpyDeviceToDevice);
    cudaMemcpy2DAsync(V, VW * sizeof(float), Bm, 64 * sizeof(float),
                      64 * sizeof(float), NST, cudaMemcpyDeviceToDevice);

    // whole stage 1 in one persistent launch
    stage1<<<NCTA, 256>>>(A, Dm);

    // tensor-core convolution (TM=256, warp tile 32t x 64o)
    conv_tc<<<dim3(SEQ / TM, BATCH), 256, SM_TOTAL>>>(x, y);
}